// round 5
// baseline (speedup 1.0000x reference)
#include <cuda_runtime.h>
#include <math_constants.h>

#define NN 100000
#define FI 256
#define FH 128
#define FO 40

typedef unsigned long long u64;

// ---------------- scratch (static device globals; zero-init at load) --------
__device__ __align__(256) float g_deg[NN];    // zero at load; re-zeroed by k_dinv
__device__ __align__(256) float g_dinv[NN];
__device__ __align__(256) float g_h1[NN * FH];
__device__ __align__(256) float g_agg1[NN * FH];
__device__ __align__(256) float g_h2[NN * FO];
__device__ __align__(256) float g_agg2[NN * FO];

// ---------------- packed fp32x2 helpers -------------------------------------
__device__ __forceinline__ u64 pack2(float lo, float hi) {
    u64 r; asm("mov.b64 %0, {%1, %2};" : "=l"(r) : "f"(lo), "f"(hi)); return r;
}
__device__ __forceinline__ float2 unpack2(u64 v) {
    float2 f; asm("mov.b64 {%0, %1}, %2;" : "=f"(f.x), "=f"(f.y) : "l"(v)); return f;
}
__device__ __forceinline__ u64 ffma2(u64 a, u64 b, u64 c) {
    u64 d; asm("fma.rn.f32x2 %0, %1, %2, %3;" : "=l"(d) : "l"(a), "l"(b), "l"(c)); return d;
}
__device__ __forceinline__ void red_add_v4(float* p, float a, float b, float c, float d) {
    asm volatile("red.global.add.v4.f32 [%0], {%1,%2,%3,%4};"
                 :: "l"(p), "f"(a), "f"(b), "f"(c), "f"(d) : "memory");
}
// per-call dtype probe: int32 data reinterpreted as int64 has random nonzero
// hi-words >= 2^32 > NN -> detected. 8 entries => P(misdetect) ~ (1e-5)^8.
__device__ __forceinline__ int probe64(const void* ei) {
    const long long* p = (const long long*)ei;
    int ok = 1;
    #pragma unroll
    for (int j = 0; j < 8; j++) {
        long long v = p[j];
        if (v < 0 || v >= NN) ok = 0;
    }
    return ok;
}
__device__ __forceinline__ int eidx(const void* p, long long i, int is64) {
    if (is64) return (int)((const long long*)p)[i];
    return ((const int*)p)[i];
}

// ---------------- degree (g_deg starts 0; cleared again by k_dinv) ----------
__global__ void k_deg_count(const void* ei, int E) {
    int i = blockIdx.x * blockDim.x + threadIdx.x;
    int is64 = probe64(ei);
    if (i < E) {
        int d = eidx(ei, (long long)E + i, is64);
        atomicAdd(&g_deg[d], 1.0f);
    }
}
__global__ void k_dinv() {
    int i = blockIdx.x * blockDim.x + threadIdx.x;
    if (i < NN) {
        float d = g_deg[i];
        g_dinv[i] = rsqrtf(d + 1.0f);   // +1 self loop; always >= 1
        g_deg[i] = 0.f;                 // restore for next graph replay
    }
}

// ---------------- GEMM1: 100000x256 @ 256x128, packed f32x2 -----------------
// 256 thr = 8 warps. Warp tg owns rows tg*16..+15 (128 rows/block).
// Lane tx owns colpairs {tx, tx+32}. K chunked by 32.
// Ws2[k][cp]: lane-consecutive 8B (conflict-free LDS.64).
// Xs2[r][k]: dup-packed, warp-uniform broadcast LDS.128 reads.
// Epilogue: h1 = acc ; agg1 = b1 + acc*dinv^2 (self-loop init).
__global__ void __launch_bounds__(256, 2) k_gemm1(const float* __restrict__ x,
                                                  const float* __restrict__ W1,
                                                  const float* __restrict__ b1) {
    __shared__ u64 Ws2[32 * 64];   // 16 KB
    __shared__ u64 Xs2[128 * 32];  // 32 KB
    int t = threadIdx.x;
    int tx = t & 31, tg = t >> 5;
    int row0 = blockIdx.x * 128;

    u64 acc[2][16];
    #pragma unroll
    for (int c = 0; c < 2; c++)
        #pragma unroll
        for (int r = 0; r < 16; r++) acc[c][r] = 0ULL;

    for (int kt = 0; kt < 8; kt++) {
        const float2* Wg = (const float2*)(W1 + (size_t)(kt * 32) * 128);
        #pragma unroll
        for (int i = t; i < 2048; i += 256) {
            float2 w = Wg[i];               // i = k*64 + cp
            Ws2[i] = pack2(w.x, w.y);
        }
        #pragma unroll
        for (int i = t; i < 4096; i += 256) {
            int r = i >> 5, k = i & 31;
            int row = row0 + r; if (row >= NN) row = NN - 1;
            float v = x[(size_t)row * FI + kt * 32 + k];
            Xs2[i] = pack2(v, v);
        }
        __syncthreads();

        #pragma unroll
        for (int k = 0; k < 32; k += 2) {
            u64 w00 = Ws2[k * 64 + tx];
            u64 w01 = Ws2[k * 64 + tx + 32];
            u64 w10 = Ws2[(k + 1) * 64 + tx];
            u64 w11 = Ws2[(k + 1) * 64 + tx + 32];
            #pragma unroll
            for (int r = 0; r < 16; r++) {
                ulonglong2 xv = *(const ulonglong2*)&Xs2[(tg * 16 + r) * 32 + k];
                acc[0][r] = ffma2(xv.x, w00, acc[0][r]);
                acc[1][r] = ffma2(xv.x, w01, acc[1][r]);
                acc[0][r] = ffma2(xv.y, w10, acc[0][r]);
                acc[1][r] = ffma2(xv.y, w11, acc[1][r]);
            }
        }
        __syncthreads();
    }

    #pragma unroll
    for (int r = 0; r < 16; r++) {
        int row = row0 + tg * 16 + r;
        if (row < NN) {
            float di = g_dinv[row];
            float di2 = di * di;
            #pragma unroll
            for (int c = 0; c < 2; c++) {
                int cp = tx + c * 32;
                float2 a = unpack2(acc[c][r]);
                ((float2*)g_h1)[(size_t)row * 64 + cp] = a;
                float2 bv = ((const float2*)b1)[cp];
                float2 o = make_float2(bv.x + a.x * di2, bv.y + a.y * di2);
                ((float2*)g_agg1)[(size_t)row * 64 + cp] = o;
            }
        }
    }
}

// ---------------- layer-1 edge scatter: warp per edge ------------------------
__global__ void k_scat1(const void* __restrict__ ei, int E) {
    int w = (blockIdx.x * blockDim.x + threadIdx.x) >> 5;
    int lane = threadIdx.x & 31;
    int is64 = probe64(ei);
    if (w < E) {
        int s = eidx(ei, w, is64);
        int d = eidx(ei, (long long)E + w, is64);
        float nm = g_dinv[s] * g_dinv[d];
        const float4* hp = (const float4*)(g_h1 + (size_t)s * FH);
        float4 v = hp[lane];
        red_add_v4(g_agg1 + (size_t)d * FH + lane * 4,
                   v.x * nm, v.y * nm, v.z * nm, v.w * nm);
    }
}

// ---------------- GEMM2: relu(agg1)[100000x128] @ W2[128x40] ----------------
// 160 thr: tx=t%20 (colpair), tg=t/20 (0..7) -> rows tg*8..+7 (64 rows/block).
// K chunked by 64. ReLU fused on X load. Epilogue: h2 ; agg2 = b2 + h2*dinv^2.
__global__ void __launch_bounds__(160) k_gemm2(const float* __restrict__ W2,
                                               const float* __restrict__ b2) {
    __shared__ u64 Ws2[64 * 20];   // 10 KB
    __shared__ u64 Xs2[64 * 64];   // 32 KB
    int t = threadIdx.x;
    int tx = t % 20, tg = t / 20;
    int row0 = blockIdx.x * 64;

    u64 acc[8];
    #pragma unroll
    for (int r = 0; r < 8; r++) acc[r] = 0ULL;

    for (int kt = 0; kt < 2; kt++) {
        const float2* Wg = (const float2*)(W2 + (size_t)(kt * 64) * 40);
        for (int i = t; i < 1280; i += 160) {
            float2 w = Wg[i];               // i = k*20 + cp
            Ws2[i] = pack2(w.x, w.y);
        }
        for (int i = t; i < 4096; i += 160) {
            int r = i >> 6, k = i & 63;
            int row = row0 + r; if (row >= NN) row = NN - 1;
            float v = fmaxf(g_agg1[(size_t)row * FH + kt * 64 + k], 0.f);
            Xs2[i] = pack2(v, v);
        }
        __syncthreads();

        #pragma unroll
        for (int k = 0; k < 64; k += 2) {
            u64 w0 = Ws2[k * 20 + tx];
            u64 w1 = Ws2[(k + 1) * 20 + tx];
            #pragma unroll
            for (int r = 0; r < 8; r++) {
                ulonglong2 xv = *(const ulonglong2*)&Xs2[(tg * 8 + r) * 64 + k];
                acc[r] = ffma2(xv.x, w0, acc[r]);
                acc[r] = ffma2(xv.y, w1, acc[r]);
            }
        }
        __syncthreads();
    }

    #pragma unroll
    for (int r = 0; r < 8; r++) {
        int row = row0 + tg * 8 + r;
        if (row < NN) {
            float di = g_dinv[row];
            float di2 = di * di;
            float2 a = unpack2(acc[r]);
            ((float2*)g_h2)[(size_t)row * 20 + tx] = a;
            float2 bv = ((const float2*)b2)[tx];
            float2 o = make_float2(bv.x + a.x * di2, bv.y + a.y * di2);
            ((float2*)g_agg2)[(size_t)row * 20 + tx] = o;
        }
    }
}

// ---------------- layer-2 edge scatter: thread per (edge, f4 chunk) ----------
__global__ void k_scat2(const void* __restrict__ ei, int E) {
    long long idx = (long long)blockIdx.x * blockDim.x + threadIdx.x;
    int is64 = probe64(ei);
    if (idx < (long long)E * 10) {
        int e = (int)(idx / 10);
        int q = (int)(idx - (long long)e * 10);
        int s = eidx(ei, e, is64);
        int d = eidx(ei, (long long)E + e, is64);
        float nm = g_dinv[s] * g_dinv[d];
        const float4* hp = (const float4*)(g_h2 + (size_t)s * FO);
        float4 v = hp[q];
        red_add_v4(g_agg2 + (size_t)d * FO + q * 4,
                   v.x * nm, v.y * nm, v.z * nm, v.w * nm);
    }
}

// ---------------- log_softmax, warp per row ----------------------------------
__global__ void k_lsm(float* __restrict__ out) {
    int row = (blockIdx.x * blockDim.x + threadIdx.x) >> 5;
    int lane = threadIdx.x & 31;
    if (row < NN) {
        const float* in = g_agg2 + (size_t)row * FO;
        float v0 = in[lane];
        float v1 = (lane < 8) ? in[32 + lane] : -CUDART_INF_F;
        float m = fmaxf(v0, v1);
        #pragma unroll
        for (int o = 16; o; o >>= 1) m = fmaxf(m, __shfl_xor_sync(0xffffffffu, m, o));
        float s = expf(v0 - m) + ((lane < 8) ? expf(v1 - m) : 0.f);
        #pragma unroll
        for (int o = 16; o; o >>= 1) s += __shfl_xor_sync(0xffffffffu, s, o);
        float ls = m + logf(s);
        out[(size_t)row * FO + lane] = v0 - ls;
        if (lane < 8) out[(size_t)row * FO + 32 + lane] = v1 - ls;
    }
}

// ---------------- launch ------------------------------------------------------
extern "C" void kernel_launch(void* const* d_in, const int* in_sizes, int n_in,
                              void* d_out, int out_size) {
    const float* x  = (const float*)d_in[0];
    const void*  ei = d_in[1];
    const float* W1 = (const float*)d_in[2];
    const float* b1 = (const float*)d_in[3];
    const float* W2 = (const float*)d_in[4];
    const float* b2 = (const float*)d_in[5];
    float* out = (float*)d_out;
    int E = in_sizes[1] / 2;

    k_deg_count<<<(E + 255) / 256, 256>>>(ei, E);                 // 0
    k_dinv<<<(NN + 255) / 256, 256>>>();                          // 1
    k_gemm1<<<(NN + 127) / 128, 256>>>(x, W1, b1);                // 2
    k_scat1<<<(E + 7) / 8, 256>>>(ei, E);                         // 3 <- ncu lands here
    k_gemm2<<<(NN + 63) / 64, 160>>>(W2, b2);                     // 4
    long long tot2 = (long long)E * 10;
    k_scat2<<<(unsigned)((tot2 + 255) / 256), 256>>>(ei, E);      // 5
    k_lsm<<<(NN + 7) / 8, 256>>>(out);                            // 6
}

// round 6
// speedup vs baseline: 1.4410x; 1.4410x over previous
#include <cuda_runtime.h>
#include <math_constants.h>

#define NN 100000
#define FI 256
#define FH 128
#define FO 40
#define EMAX 1700000

typedef unsigned long long u64;

// ---------------- scratch (static device globals; zero-init at load) --------
__device__ int   g_cnt[NN];        // degree counts (restored to 0 each call)
__device__ int   g_rowp[NN];       // CSR row start
__device__ int   g_cur[NN];        // fill cursor; after fill == row end
__device__ int   g_nbr[EMAX];      // CSR neighbor (src) ids
__device__ int   g_alloc;          // row allocation cursor
__device__ __align__(256) float g_dinv[NN];
__device__ __align__(256) float g_h1[NN * FH];
__device__ __align__(256) float g_agg1[NN * FH];
__device__ __align__(256) float g_h2[NN * FO];
__device__ __align__(256) float g_agg2[NN * FO];

// ---------------- packed fp32x2 helpers -------------------------------------
__device__ __forceinline__ u64 pack2(float lo, float hi) {
    u64 r; asm("mov.b64 %0, {%1, %2};" : "=l"(r) : "f"(lo), "f"(hi)); return r;
}
__device__ __forceinline__ float2 unpack2(u64 v) {
    float2 f; asm("mov.b64 {%0, %1}, %2;" : "=f"(f.x), "=f"(f.y) : "l"(v)); return f;
}
__device__ __forceinline__ u64 ffma2(u64 a, u64 b, u64 c) {
    u64 d; asm("fma.rn.f32x2 %0, %1, %2, %3;" : "=l"(d) : "l"(a), "l"(b), "l"(c)); return d;
}
// dtype probe: int32 data viewed as int64 has random hi-words -> out of range.
// Only used in thread-per-edge kernels (warp-broadcast loads, ~free).
__device__ __forceinline__ int probe64(const void* ei) {
    const long long* p = (const long long*)ei;
    int ok = 1;
    #pragma unroll
    for (int j = 0; j < 8; j++) {
        long long v = p[j];
        if (v < 0 || v >= NN) ok = 0;
    }
    return ok;
}
__device__ __forceinline__ int eidx(const void* p, long long i, int is64) {
    if (is64) return (int)((const long long*)p)[i];
    return ((const int*)p)[i];
}

// ---------------- CSR build --------------------------------------------------
__global__ void k_deg(const void* ei, int E) {
    int i = blockIdx.x * blockDim.x + threadIdx.x;
    if (i == 0) g_alloc = 0;                     // reset allocator (pre-rowp)
    int is64 = probe64(ei);
    if (i < E) {
        int d = eidx(ei, (long long)E + i, is64);
        atomicAdd(&g_cnt[d], 1);
    }
}

__global__ void k_rowp() {
    int i = blockIdx.x * blockDim.x + threadIdx.x;
    if (i < NN) {
        int c = g_cnt[i];
        int start = atomicAdd(&g_alloc, c);      // order-free row allocation
        g_rowp[i] = start;
        g_cur[i]  = start;
        g_dinv[i] = rsqrtf((float)c + 1.0f);     // +1 self loop
        g_cnt[i]  = 0;                           // restore for next call
    }
}

__global__ void k_fill(const void* ei, int E) {
    int i = blockIdx.x * blockDim.x + threadIdx.x;
    int is64 = probe64(ei);
    if (i < E) {
        int s = eidx(ei, i, is64);
        int d = eidx(ei, (long long)E + i, is64);
        int p = atomicAdd(&g_cur[d], 1);
        g_nbr[p] = s;
    }
}

// ---------------- GEMM1: h1 = x @ W1  (100000x256 @ 256x128) ----------------
// 256 thr = 8 warps; warp tg rows tg*16..+15 (128 rows/blk); lane tx colpairs
// {tx, tx+32}. Ws2[k][cp] conflict-free LDS.64; Xs2[r][k] dup-pack broadcast.
__global__ void __launch_bounds__(256, 2) k_gemm1(const float* __restrict__ x,
                                                  const float* __restrict__ W1) {
    __shared__ u64 Ws2[32 * 64];   // 16 KB
    __shared__ u64 Xs2[128 * 32];  // 32 KB
    int t = threadIdx.x;
    int tx = t & 31, tg = t >> 5;
    int row0 = blockIdx.x * 128;

    u64 acc[2][16];
    #pragma unroll
    for (int c = 0; c < 2; c++)
        #pragma unroll
        for (int r = 0; r < 16; r++) acc[c][r] = 0ULL;

    for (int kt = 0; kt < 8; kt++) {
        const float2* Wg = (const float2*)(W1 + (size_t)(kt * 32) * 128);
        #pragma unroll
        for (int i = t; i < 2048; i += 256) {
            float2 w = Wg[i];               // i = k*64 + cp
            Ws2[i] = pack2(w.x, w.y);
        }
        #pragma unroll
        for (int i = t; i < 4096; i += 256) {
            int r = i >> 5, k = i & 31;
            int row = row0 + r; if (row >= NN) row = NN - 1;
            float v = x[(size_t)row * FI + kt * 32 + k];
            Xs2[i] = pack2(v, v);
        }
        __syncthreads();

        #pragma unroll
        for (int k = 0; k < 32; k += 2) {
            u64 w00 = Ws2[k * 64 + tx];
            u64 w01 = Ws2[k * 64 + tx + 32];
            u64 w10 = Ws2[(k + 1) * 64 + tx];
            u64 w11 = Ws2[(k + 1) * 64 + tx + 32];
            #pragma unroll
            for (int r = 0; r < 16; r++) {
                ulonglong2 xv = *(const ulonglong2*)&Xs2[(tg * 16 + r) * 32 + k];
                acc[0][r] = ffma2(xv.x, w00, acc[0][r]);
                acc[1][r] = ffma2(xv.x, w01, acc[1][r]);
                acc[0][r] = ffma2(xv.y, w10, acc[0][r]);
                acc[1][r] = ffma2(xv.y, w11, acc[1][r]);
            }
        }
        __syncthreads();
    }

    #pragma unroll
    for (int r = 0; r < 16; r++) {
        int row = row0 + tg * 16 + r;
        if (row < NN) {
            #pragma unroll
            for (int c = 0; c < 2; c++) {
                ((float2*)g_h1)[(size_t)row * 64 + tx + c * 32] = unpack2(acc[c][r]);
            }
        }
    }
}

// ---------------- layer-1 aggregate: warp-per-dst CSR gather -----------------
// agg1[d] = b1 + dinv[d]^2 * h1[d] + sum_{s in N(d)} dinv[d]*dinv[s]*h1[s]
__global__ void __launch_bounds__(256) k_agg1(const float* __restrict__ b1) {
    int w = (blockIdx.x * 256 + threadIdx.x) >> 5;
    int lane = threadIdx.x & 31;
    if (w >= NN) return;
    int e = g_rowp[w], end = g_cur[w];
    float did = g_dinv[w];
    const float4* H = (const float4*)g_h1;

    float4 acc = ((const float4*)b1)[lane];
    float4 self = H[(size_t)w * 32 + lane];
    float d2 = did * did;
    acc.x = fmaf(self.x, d2, acc.x);
    acc.y = fmaf(self.y, d2, acc.y);
    acc.z = fmaf(self.z, d2, acc.z);
    acc.w = fmaf(self.w, d2, acc.w);

    // software-pipelined neighbor loop
    int s = (e < end) ? g_nbr[e] : 0;
    while (e < end) {
        int sn = (e + 1 < end) ? g_nbr[e + 1] : 0;
        float nm = did * g_dinv[s];
        float4 v = H[(size_t)s * 32 + lane];
        acc.x = fmaf(v.x, nm, acc.x);
        acc.y = fmaf(v.y, nm, acc.y);
        acc.z = fmaf(v.z, nm, acc.z);
        acc.w = fmaf(v.w, nm, acc.w);
        s = sn;
        e++;
    }
    ((float4*)g_agg1)[(size_t)w * 32 + lane] = acc;
}

// ---------------- GEMM2: h2 = relu(agg1) @ W2  (100000x128 @ 128x40) --------
__global__ void __launch_bounds__(160) k_gemm2(const float* __restrict__ W2) {
    __shared__ u64 Ws2[64 * 20];   // 10 KB
    __shared__ u64 Xs2[64 * 64];   // 32 KB
    int t = threadIdx.x;
    int tx = t % 20, tg = t / 20;
    int row0 = blockIdx.x * 64;

    u64 acc[8];
    #pragma unroll
    for (int r = 0; r < 8; r++) acc[r] = 0ULL;

    for (int kt = 0; kt < 2; kt++) {
        const float2* Wg = (const float2*)(W2 + (size_t)(kt * 64) * 40);
        for (int i = t; i < 1280; i += 160) {
            float2 w = Wg[i];               // i = k*20 + cp
            Ws2[i] = pack2(w.x, w.y);
        }
        for (int i = t; i < 4096; i += 160) {
            int r = i >> 6, k = i & 63;
            int row = row0 + r; if (row >= NN) row = NN - 1;
            float v = fmaxf(g_agg1[(size_t)row * FH + kt * 64 + k], 0.f);
            Xs2[i] = pack2(v, v);
        }
        __syncthreads();

        #pragma unroll
        for (int k = 0; k < 64; k += 2) {
            u64 w0 = Ws2[k * 20 + tx];
            u64 w1 = Ws2[(k + 1) * 20 + tx];
            #pragma unroll
            for (int r = 0; r < 8; r++) {
                ulonglong2 xv = *(const ulonglong2*)&Xs2[(tg * 8 + r) * 64 + k];
                acc[r] = ffma2(xv.x, w0, acc[r]);
                acc[r] = ffma2(xv.y, w1, acc[r]);
            }
        }
        __syncthreads();
    }

    #pragma unroll
    for (int r = 0; r < 8; r++) {
        int row = row0 + tg * 8 + r;
        if (row < NN)
            ((float2*)g_h2)[(size_t)row * 20 + tx] = unpack2(acc[r]);
    }
}

// ---------------- layer-2 aggregate: 10-threads-per-dst CSR gather -----------
__global__ void __launch_bounds__(320) k_agg2(const float* __restrict__ b2) {
    int idx = blockIdx.x * 320 + threadIdx.x;
    int w = idx / 10, c = idx % 10;
    if (w >= NN) return;
    int e = g_rowp[w], end = g_cur[w];
    float did = g_dinv[w];
    const float4* H = (const float4*)g_h2;

    float4 acc = ((const float4*)b2)[c];
    float4 self = H[(size_t)w * 10 + c];
    float d2 = did * did;
    acc.x = fmaf(self.x, d2, acc.x);
    acc.y = fmaf(self.y, d2, acc.y);
    acc.z = fmaf(self.z, d2, acc.z);
    acc.w = fmaf(self.w, d2, acc.w);

    int s = (e < end) ? g_nbr[e] : 0;
    while (e < end) {
        int sn = (e + 1 < end) ? g_nbr[e + 1] : 0;
        float nm = did * g_dinv[s];
        float4 v = H[(size_t)s * 10 + c];
        acc.x = fmaf(v.x, nm, acc.x);
        acc.y = fmaf(v.y, nm, acc.y);
        acc.z = fmaf(v.z, nm, acc.z);
        acc.w = fmaf(v.w, nm, acc.w);
        s = sn;
        e++;
    }
    ((float4*)g_agg2)[(size_t)w * 10 + c] = acc;
}

// ---------------- log_softmax, warp per row ----------------------------------
__global__ void k_lsm(float* __restrict__ out) {
    int row = (blockIdx.x * blockDim.x + threadIdx.x) >> 5;
    int lane = threadIdx.x & 31;
    if (row < NN) {
        const float* in = g_agg2 + (size_t)row * FO;
        float v0 = in[lane];
        float v1 = (lane < 8) ? in[32 + lane] : -CUDART_INF_F;
        float m = fmaxf(v0, v1);
        #pragma unroll
        for (int o = 16; o; o >>= 1) m = fmaxf(m, __shfl_xor_sync(0xffffffffu, m, o));
        float s = expf(v0 - m) + ((lane < 8) ? expf(v1 - m) : 0.f);
        #pragma unroll
        for (int o = 16; o; o >>= 1) s += __shfl_xor_sync(0xffffffffu, s, o);
        float ls = m + logf(s);
        out[(size_t)row * FO + lane] = v0 - ls;
        if (lane < 8) out[(size_t)row * FO + 32 + lane] = v1 - ls;
    }
}

// ---------------- launch ------------------------------------------------------
extern "C" void kernel_launch(void* const* d_in, const int* in_sizes, int n_in,
                              void* d_out, int out_size) {
    const float* x  = (const float*)d_in[0];
    const void*  ei = d_in[1];
    const float* W1 = (const float*)d_in[2];
    const float* b1 = (const float*)d_in[3];
    const float* W2 = (const float*)d_in[4];
    const float* b2 = (const float*)d_in[5];
    float* out = (float*)d_out;
    int E = in_sizes[1] / 2;
    if (E > EMAX) E = EMAX;  // safety (dataset E = 1.6M)

    k_deg<<<(E + 255) / 256, 256>>>(ei, E);            // 0
    k_rowp<<<(NN + 255) / 256, 256>>>();               // 1
    k_fill<<<(E + 255) / 256, 256>>>(ei, E);           // 2
    k_gemm1<<<(NN + 127) / 128, 256>>>(x, W1);         // 3 <- ncu window
    k_agg1<<<(NN + 7) / 8, 256>>>(b1);                 // 4
    k_gemm2<<<(NN + 63) / 64, 160>>>(W2);              // 5
    k_agg2<<<(NN * 10 + 319) / 320, 320>>>(b2);        // 6
    k_lsm<<<(NN + 7) / 8, 256>>>(out);                 // 7
}